// round 3
// baseline (speedup 1.0000x reference)
#include <cuda_runtime.h>
#include <math.h>

// Problem constants (fixed by the reference's setup_inputs)
#define BB   4
#define NN   2048
#define MO   32
#define DD   256
#define NTOK (BB*NN)            // 8192
#define TOKF (MO*DD)            // 8192 floats per token per buffer
#define TOKP (TOKF/2)           // 4096 float2-pairs per token
#define NCOMBO 2178             // 33*33*2 distinct (lc, rc, sub) combos
#define SCAN_BLOCKS 256

typedef unsigned long long ull;

// -------- device globals (scratch; no allocations allowed) --------
__device__ int   g_mode;              // 2 = structured const-A, 1 = const dense A, 0 = per-combo table
__device__ int   g_blknz[SCAN_BLOCKS];// per-block W3-nonzero flags (overwritten each replay; no reset kernel)
__device__ float g_off, g_dd;         // mode-2 constants: off-diag value, (diag - off)
__device__ ull   g_A2[NCOMBO][MO*2*MO]; // attn table, each entry = value duplicated as f32x2

// -------- packed f32x2 helpers (SASS: FFMA2 / FADD2 / FMUL2) --------
__device__ __forceinline__ ull pack2(float x, float y) {
    ull u; asm("mov.b64 %0, {%1,%2};" : "=l"(u) : "f"(x), "f"(y)); return u;
}
__device__ __forceinline__ void ffma2(ull &d, ull a, ull b) {
    asm("fma.rn.f32x2 %0, %1, %2, %0;" : "+l"(d) : "l"(a), "l"(b));
}
__device__ __forceinline__ ull add2(ull a, ull b) {
    ull d; asm("add.rn.f32x2 %0, %1, %2;" : "=l"(d) : "l"(a), "l"(b)); return d;
}
__device__ __forceinline__ ull mul2(ull a, ull b) {
    ull d; asm("mul.rn.f32x2 %0, %1, %2;" : "=l"(d) : "l"(a), "l"(b)); return d;
}
// streaming (evict-first) global access — data is read-once/write-once
__device__ __forceinline__ ull ldcs(const ull* p) {
    ull v; asm("ld.global.cs.b64 %0, [%1];" : "=l"(v) : "l"(p)); return v;
}
__device__ __forceinline__ void stcs(ull* p, ull v) {
    asm volatile("st.global.cs.b64 [%0], %1;" :: "l"(p), "l"(v) : "memory");
}

// ================= kernel A: parallel scan of W3 (per-block flags) =================
__global__ void scan_w3_kernel(const float* __restrict__ W3, int n) {
    bool nz = false;
    for (int i = blockIdx.x * blockDim.x + threadIdx.x; i < n; i += gridDim.x * blockDim.x)
        nz |= (W3[i] != 0.0f);
    int b = __syncthreads_or(nz);
    if (threadIdx.x == 0) g_blknz[blockIdx.x] = b;
}

// ====== kernel B: softmax(b3 rows), structure check, pick mode ======
// 1 block, 1024 threads. Rows p = warp id (32 warps), lanes cover cols q and q+32.
__global__ void finalize_kernel(const float* __restrict__ b3) {
    __shared__ float sA[MO*2*MO]; // 32 x 64 probs
    int tid = threadIdx.x;
    int w = tid >> 5, lane = tid & 31;

    // reduce the per-block W3 flags
    int w3nz = __syncthreads_or(tid < SCAN_BLOCKS ? g_blknz[tid] : 0);

    {
        float v0 = b3[w*64 + lane];
        float v1 = b3[w*64 + 32 + lane];
        float m = fmaxf(v0, v1);
        #pragma unroll
        for (int o = 16; o; o >>= 1) m = fmaxf(m, __shfl_xor_sync(0xffffffffu, m, o));
        float e0 = expf(v0 - m), e1 = expf(v1 - m);
        float s = e0 + e1;
        #pragma unroll
        for (int o = 16; o; o >>= 1) s += __shfl_xor_sync(0xffffffffu, s, o);
        sA[w*64 + lane]      = e0 / s;
        sA[w*64 + 32 + lane] = e1 / s;
    }
    __syncthreads();

    // structure check: A[p][q] == (p==q ? diag : off), shared diag/off across rows
    float rdiag = sA[0], roff = sA[1];
    bool ok = true;
    for (int i = tid; i < MO*2*MO; i += 1024) {
        int p = i >> 6, q = i & 63;
        ok &= (sA[i] == ((q == p) ? rdiag : roff));
    }
    int all_ok = __syncthreads_and(ok);

    // write A2[0] (used by mode 1; overwritten by combo kernel in mode 0)
    for (int i = tid; i < MO*2*MO; i += 1024) {
        float v = sA[i];
        g_A2[0][i] = pack2(v, v);
    }
    if (tid == 0) {
        g_mode = w3nz ? 0 : (all_ok ? 2 : 1);
        g_off  = roff;
        g_dd   = rdiag - roff;
    }
}

// ===== kernel C: per-combo MLP -> attn table (persistent; only does work if mode==0) =====
// grid = 148 blocks x 256 threads looping over NCOMBO combos. Never taken for the real
// inputs (W3==0); kept as the generic-correctness fallback.
__global__ void combo_kernel(const float* __restrict__ W1, const float* __restrict__ b1,
                             const float* __restrict__ W2, const float* __restrict__ b2,
                             const float* __restrict__ W3, const float* __restrict__ b3) {
    if (g_mode != 0) return;
    __shared__ float h1[256], h2[256], lg[2048];
    int j = threadIdx.x;
    const float RS2 = 0.70710678118654752f;

    for (int idx = blockIdx.x; idx < NCOMBO; idx += gridDim.x) {
        int l = idx / 66, rem = idx % 66;
        int r = rem >> 1, s = rem & 1;
        float f0 = l * (1.0f/32.0f), f1 = r * (1.0f/32.0f);
        float f2 = (s == 0) ? 1.0f : 0.0f, f3 = (s == 1) ? 1.0f : 0.0f;
        {
            float a = b1[j] + W1[j*4]*f0 + W1[j*4+1]*f1 + W1[j*4+2]*f2 + W1[j*4+3]*f3;
            h1[j] = 0.5f * a * (1.0f + erff(a * RS2));
        }
        __syncthreads();
        {
            float a = b2[j];
            for (int k = 0; k < 256; k++) a += W2[j*256 + k] * h1[k];
            h2[j] = 0.5f * a * (1.0f + erff(a * RS2));
        }
        __syncthreads();
        for (int m = 0; m < 8; m++) {
            int o = m*256 + j;
            float a = b3[o];
            for (int k = 0; k < 256; k++) a += W3[o*256 + k] * h2[k];
            lg[o] = a;
        }
        __syncthreads();
        int w = j >> 5, lane = j & 31;
        for (int rr = 0; rr < 4; rr++) {
            int p = w*4 + rr;
            float v0 = lg[p*64 + lane], v1 = lg[p*64 + 32 + lane];
            float mx = fmaxf(v0, v1);
            #pragma unroll
            for (int o = 16; o; o >>= 1) mx = fmaxf(mx, __shfl_xor_sync(0xffffffffu, mx, o));
            float e0 = expf(v0 - mx), e1 = expf(v1 - mx);
            float sm = e0 + e1;
            #pragma unroll
            for (int o = 16; o; o >>= 1) sm += __shfl_xor_sync(0xffffffffu, sm, o);
            float p0 = e0 / sm, p1 = e1 / sm;
            g_A2[idx][p*64 + lane]      = pack2(p0, p0);
            g_A2[idx][p*64 + 32 + lane] = pack2(p1, p1);
        }
        __syncthreads();
    }
}

// ================= kernel D: main combine (einsum) =================
// One CTA per token, 128 threads; thread t owns d-pair column t (2 floats, f32x2).
__global__ void __launch_bounds__(128) combine_kernel(
    const float* __restrict__ L, const float* __restrict__ lcnt,
    const float* __restrict__ R, const float* __restrict__ rcnt,
    const int*   __restrict__ subs,
    float* __restrict__ out_buf, float* __restrict__ out_cnt)
{
    __shared__ ull sA[MO*2*MO];  // duplicated-pair attn matrix (16 KB, generic path only)
    int token = blockIdx.x;
    int t = threadIdx.x;
    int mode = g_mode;

    const ull* Lp = reinterpret_cast<const ull*>(L) + (size_t)token * TOKP;
    const ull* Rp = reinterpret_cast<const ull*>(R) + (size_t)token * TOKP;
    ull*       O  = reinterpret_cast<ull*>(out_buf) + (size_t)token * TOKP;

    if (t == 0)
        out_cnt[token] = fminf(lcnt[token] + rcnt[token], (float)MO);

    if (mode == 2) {
        // out[p] = (diag-off) * L[p] + off * S,  S = sum over all 64 concat rows.
        // Purely memory-bound: each element touched exactly once.
        // Loads chunked in groups of 8 (MLP_p1 ~ 8) to limit cross-CTA L1tex-queue spread.
        float offv = g_off, ddv = g_dd;
        ull off2 = pack2(offv, offv), dd2 = pack2(ddv, ddv);
        ull S = 0ull;
        ull acc[32];
        #pragma unroll 1
        for (int qc = 0; qc < 4; qc++) {
            ull c[8];
            #pragma unroll
            for (int i = 0; i < 8; i++) c[i] = ldcs(&Lp[(qc*8 + i)*128 + t]);
            #pragma unroll
            for (int i = 0; i < 8; i++) {
                S = add2(S, c[i]);
                acc[qc*8 + i] = mul2(dd2, c[i]);
            }
        }
        #pragma unroll 1
        for (int qc = 0; qc < 4; qc++) {
            ull c[8];
            #pragma unroll
            for (int i = 0; i < 8; i++) c[i] = ldcs(&Rp[(qc*8 + i)*128 + t]);
            #pragma unroll
            for (int i = 0; i < 8; i++) S = add2(S, c[i]);
        }
        #pragma unroll 1
        for (int pc = 0; pc < 4; pc++) {
            #pragma unroll
            for (int i = 0; i < 8; i++) {
                int p = pc*8 + i;
                ull res = acc[p];
                ffma2(res, off2, S);
                stcs(&O[p*128 + t], res);
            }
        }
        return;
    }

    // Generic dense path: mode 1 (single A, idx 0) or mode 0 (per-token combo).
    int idx = 0;
    if (mode == 0) {
        int l = (int)lcnt[token];
        int r = (int)rcnt[token];
        int s = subs[token]; s = s < 0 ? 0 : (s > 1 ? 1 : s);
        idx = l*66 + r*2 + s;
    }
    {
        const ulonglong2* src = reinterpret_cast<const ulonglong2*>(g_A2[idx]);
        ulonglong2*       dst = reinterpret_cast<ulonglong2*>(sA);
        for (int i = t; i < (MO*2*MO)/2; i += 128) dst[i] = src[i];
    }
    __syncthreads();

    ull acc[32];
    #pragma unroll
    for (int p = 0; p < 32; p++) acc[p] = 0ull;

    #pragma unroll 1
    for (int half = 0; half < 2; half++) {
        const ull* C = half ? Rp : Lp;
        #pragma unroll 1
        for (int qc = 0; qc < 2; qc++) {
            ull c[16];
            #pragma unroll
            for (int i = 0; i < 16; i++) c[i] = C[(qc*16 + i)*128 + t];
            int qb = half*32 + qc*16;
            #pragma unroll
            for (int p = 0; p < 32; p++) {
                #pragma unroll
                for (int i = 0; i < 16; i += 2) {
                    ulonglong2 a = *reinterpret_cast<const ulonglong2*>(&sA[p*64 + qb + i]);
                    ffma2(acc[p], a.x, c[i]);
                    ffma2(acc[p], a.y, c[i+1]);
                }
            }
        }
    }
    #pragma unroll
    for (int p = 0; p < 32; p++) O[p*128 + t] = acc[p];
}

// ============================ launch ============================
extern "C" void kernel_launch(void* const* d_in, const int* in_sizes, int n_in,
                              void* d_out, int out_size) {
    const float* L    = (const float*)d_in[0];
    const float* lcnt = (const float*)d_in[1];
    const float* R    = (const float*)d_in[2];
    const float* rcnt = (const float*)d_in[3];
    const int*   subs = (const int*)  d_in[4];
    const float* W1   = (const float*)d_in[5];
    const float* b1   = (const float*)d_in[6];
    const float* W2   = (const float*)d_in[7];
    const float* b2   = (const float*)d_in[8];
    const float* W3   = (const float*)d_in[9];
    const float* b3   = (const float*)d_in[10];

    float* out = (float*)d_out;
    int ntok = in_sizes[1];                           // B*N = 8192
    float* out_cnt = out + ((size_t)out_size - ntok); // new_buf first, new_count last
    int w3n = in_sizes[9];                            // 2048*256

    scan_w3_kernel<<<SCAN_BLOCKS, 1024>>>(W3, w3n);
    finalize_kernel<<<1, 1024>>>(b3);
    combo_kernel<<<148, 256>>>(W1, b1, W2, b2, W3, b3);
    combine_kernel<<<ntok, 128>>>(L, lcnt, R, rcnt, subs, out, out_cnt);
}

// round 4
// speedup vs baseline: 1.2340x; 1.2340x over previous
#include <cuda_runtime.h>
#include <math.h>

// Problem constants (fixed by the reference's setup_inputs)
#define BB   4
#define NN   2048
#define MO   32
#define DD   256
#define NTOK (BB*NN)            // 8192
#define TOKF (MO*DD)            // 8192 floats per token per buffer
#define TOKP (TOKF/2)           // 4096 float2-pairs per token
#define NCOMBO 2178             // 33*33*2 distinct (lc, rc, sub) combos
#define SCAN_BLOCKS 256

typedef unsigned long long ull;

// -------- device globals (scratch; no allocations allowed) --------
__device__ int   g_mode;              // 2 = structured const-A, 1 = const dense A, 0 = per-combo table
__device__ int   g_blknz[SCAN_BLOCKS];// per-block W3-nonzero flags (overwritten each replay)
__device__ float g_off, g_dd;         // mode-2 constants: off-diag value, (diag - off)
__device__ ull   g_A2[NCOMBO][MO*2*MO]; // attn table, each entry = value duplicated as f32x2

// -------- packed f32x2 helpers (SASS: FFMA2 / FADD2 / FMUL2) --------
__device__ __forceinline__ ull pack2(float x, float y) {
    ull u; asm("mov.b64 %0, {%1,%2};" : "=l"(u) : "f"(x), "f"(y)); return u;
}
__device__ __forceinline__ void ffma2(ull &d, ull a, ull b) {
    asm("fma.rn.f32x2 %0, %1, %2, %0;" : "+l"(d) : "l"(a), "l"(b));
}
__device__ __forceinline__ ull add2(ull a, ull b) {
    ull d; asm("add.rn.f32x2 %0, %1, %2;" : "=l"(d) : "l"(a), "l"(b)); return d;
}
__device__ __forceinline__ ull mul2(ull a, ull b) {
    ull d; asm("mul.rn.f32x2 %0, %1, %2;" : "=l"(d) : "l"(a), "l"(b)); return d;
}

// ================= kernel A: parallel scan of W3 (per-block flags) =================
__global__ void scan_w3_kernel(const float* __restrict__ W3, int n) {
    bool nz = false;
    for (int i = blockIdx.x * blockDim.x + threadIdx.x; i < n; i += gridDim.x * blockDim.x)
        nz |= (W3[i] != 0.0f);
    int b = __syncthreads_or(nz);
    if (threadIdx.x == 0) g_blknz[blockIdx.x] = b;
}

// ====== kernel B: softmax(b3 rows), structure check, pick mode ======
__global__ void finalize_kernel(const float* __restrict__ b3) {
    __shared__ float sA[MO*2*MO]; // 32 x 64 probs
    int tid = threadIdx.x;
    int w = tid >> 5, lane = tid & 31;

    int w3nz = __syncthreads_or(tid < SCAN_BLOCKS ? g_blknz[tid] : 0);

    {
        float v0 = b3[w*64 + lane];
        float v1 = b3[w*64 + 32 + lane];
        float m = fmaxf(v0, v1);
        #pragma unroll
        for (int o = 16; o; o >>= 1) m = fmaxf(m, __shfl_xor_sync(0xffffffffu, m, o));
        float e0 = expf(v0 - m), e1 = expf(v1 - m);
        float s = e0 + e1;
        #pragma unroll
        for (int o = 16; o; o >>= 1) s += __shfl_xor_sync(0xffffffffu, s, o);
        sA[w*64 + lane]      = e0 / s;
        sA[w*64 + 32 + lane] = e1 / s;
    }
    __syncthreads();

    float rdiag = sA[0], roff = sA[1];
    bool ok = true;
    for (int i = tid; i < MO*2*MO; i += 1024) {
        int p = i >> 6, q = i & 63;
        ok &= (sA[i] == ((q == p) ? rdiag : roff));
    }
    int all_ok = __syncthreads_and(ok);

    for (int i = tid; i < MO*2*MO; i += 1024) {
        float v = sA[i];
        g_A2[0][i] = pack2(v, v);
    }
    if (tid == 0) {
        g_mode = w3nz ? 0 : (all_ok ? 2 : 1);
        g_off  = roff;
        g_dd   = rdiag - roff;
    }
}

// ===== kernel C: per-combo MLP -> attn table (persistent; only works if mode==0) =====
__global__ void combo_kernel(const float* __restrict__ W1, const float* __restrict__ b1,
                             const float* __restrict__ W2, const float* __restrict__ b2,
                             const float* __restrict__ W3, const float* __restrict__ b3) {
    if (g_mode != 0) return;
    __shared__ float h1[256], h2[256], lg[2048];
    int j = threadIdx.x;
    const float RS2 = 0.70710678118654752f;

    for (int idx = blockIdx.x; idx < NCOMBO; idx += gridDim.x) {
        int l = idx / 66, rem = idx % 66;
        int r = rem >> 1, s = rem & 1;
        float f0 = l * (1.0f/32.0f), f1 = r * (1.0f/32.0f);
        float f2 = (s == 0) ? 1.0f : 0.0f, f3 = (s == 1) ? 1.0f : 0.0f;
        {
            float a = b1[j] + W1[j*4]*f0 + W1[j*4+1]*f1 + W1[j*4+2]*f2 + W1[j*4+3]*f3;
            h1[j] = 0.5f * a * (1.0f + erff(a * RS2));
        }
        __syncthreads();
        {
            float a = b2[j];
            for (int k = 0; k < 256; k++) a += W2[j*256 + k] * h1[k];
            h2[j] = 0.5f * a * (1.0f + erff(a * RS2));
        }
        __syncthreads();
        for (int m = 0; m < 8; m++) {
            int o = m*256 + j;
            float a = b3[o];
            for (int k = 0; k < 256; k++) a += W3[o*256 + k] * h2[k];
            lg[o] = a;
        }
        __syncthreads();
        int w = j >> 5, lane = j & 31;
        for (int rr = 0; rr < 4; rr++) {
            int p = w*4 + rr;
            float v0 = lg[p*64 + lane], v1 = lg[p*64 + 32 + lane];
            float mx = fmaxf(v0, v1);
            #pragma unroll
            for (int o = 16; o; o >>= 1) mx = fmaxf(mx, __shfl_xor_sync(0xffffffffu, mx, o));
            float e0 = expf(v0 - mx), e1 = expf(v1 - mx);
            float sm = e0 + e1;
            #pragma unroll
            for (int o = 16; o; o >>= 1) sm += __shfl_xor_sync(0xffffffffu, sm, o);
            float p0 = e0 / sm, p1 = e1 / sm;
            g_A2[idx][p*64 + lane]      = pack2(p0, p0);
            g_A2[idx][p*64 + 32 + lane] = pack2(p1, p1);
        }
        __syncthreads();
    }
}

// ================= kernel D: main combine =================
// One CTA per token, 256 threads. Thread t = (column c = t&127, half g = t>>7).
// L tile staged in SMEM (not registers) -> low regs, high occupancy, high MLP.
__global__ void __launch_bounds__(256, 5) combine_kernel(
    const float* __restrict__ L, const float* __restrict__ lcnt,
    const float* __restrict__ R, const float* __restrict__ rcnt,
    const int*   __restrict__ subs,
    float* __restrict__ out_buf, float* __restrict__ out_cnt)
{
    __shared__ ull sL[32*128];   // 32 KB: mode2 = L tile; generic = sA(16KB) + 16-row stage(16KB)
    __shared__ ull sS[2*128];    // 2 KB : per-half column sums

    int token = blockIdx.x;
    int t = threadIdx.x;
    int c = t & 127, g = t >> 7;
    int mode = g_mode;

    const ull* Lp = reinterpret_cast<const ull*>(L) + (size_t)token * TOKP;
    const ull* Rp = reinterpret_cast<const ull*>(R) + (size_t)token * TOKP;
    ull*       O  = reinterpret_cast<ull*>(out_buf) + (size_t)token * TOKP;

    if (t == 0)
        out_cnt[token] = fminf(lcnt[token] + rcnt[token], (float)MO);

    if (mode == 2) {
        // out[p] = (diag-off)*L[p] + off*S, S = sum over all 64 concat rows (per column).
        const ull* P = (g ? Rp : Lp) + c;
        ull S = 0ull;
        #pragma unroll 1
        for (int qc = 0; qc < 4; qc++) {
            ull v[8];
            #pragma unroll
            for (int i = 0; i < 8; i++) v[i] = P[(qc*8 + i)*128];
            #pragma unroll
            for (int i = 0; i < 8; i++) {
                S = add2(S, v[i]);
                if (g == 0) sL[(qc*8 + i)*128 + c] = v[i];
            }
        }
        sS[g*128 + c] = S;
        __syncthreads();
        ull Sf = add2(sS[c], sS[128 + c]);

        float offv = g_off, ddv = g_dd;
        ull off2 = pack2(offv, offv), dd2 = pack2(ddv, ddv);
        int pbase = g * 16;
        #pragma unroll
        for (int i = 0; i < 16; i++) {
            ull res = mul2(dd2, sL[(pbase + i)*128 + c]);
            ffma2(res, off2, Sf);
            O[(pbase + i)*128 + c] = res;
        }
        return;
    }

    // ---- Generic dense path: mode 1 (single A) or mode 0 (per-token combo) ----
    int idx = 0;
    if (mode == 0) {
        int l = (int)lcnt[token];
        int r = (int)rcnt[token];
        int s = subs[token]; s = s < 0 ? 0 : (s > 1 ? 1 : s);
        idx = l*66 + r*2 + s;
    }
    ull* sAv   = sL;          // [0..2047]   : attn matrix (2048 ull)
    ull* stage = sL + 2048;   // [2048..4095]: 16-row staging (2048 ull)
    {
        const ull* src = g_A2[idx];
        #pragma unroll
        for (int i = 0; i < 8; i++) sAv[i*256 + t] = src[i*256 + t];
    }
    __syncthreads();

    ull acc[16];
    #pragma unroll
    for (int i = 0; i < 16; i++) acc[i] = 0ull;

    // 4 waves of 16 concat rows each; waves 0-1 = L rows, waves 2-3 = R rows.
    #pragma unroll 1
    for (int wv = 0; wv < 4; wv++) {
        const ull* P = (wv < 2 ? Lp : Rp) + ((wv & 1) * 16) * 128 + c;
        // each thread loads 8 rows of this wave (g picks which 8)
        #pragma unroll
        for (int i = 0; i < 8; i++) {
            int r = g*8 + i;
            stage[r*128 + c] = P[r*128];
        }
        __syncthreads();
        int qbase = wv * 16;
        #pragma unroll 1
        for (int r = 0; r < 16; r++) {
            ull v = stage[r*128 + c];
            int q = qbase + r;
            #pragma unroll
            for (int p = 0; p < 16; p++)
                ffma2(acc[p], sAv[(g*16 + p)*64 + q], v);
        }
        __syncthreads();
    }
    #pragma unroll
    for (int p = 0; p < 16; p++)
        O[(g*16 + p)*128 + c] = acc[p];
}

// ============================ launch ============================
extern "C" void kernel_launch(void* const* d_in, const int* in_sizes, int n_in,
                              void* d_out, int out_size) {
    const float* L    = (const float*)d_in[0];
    const float* lcnt = (const float*)d_in[1];
    const float* R    = (const float*)d_in[2];
    const float* rcnt = (const float*)d_in[3];
    const int*   subs = (const int*)  d_in[4];
    const float* W1   = (const float*)d_in[5];
    const float* b1   = (const float*)d_in[6];
    const float* W2   = (const float*)d_in[7];
    const float* b2   = (const float*)d_in[8];
    const float* W3   = (const float*)d_in[9];
    const float* b3   = (const float*)d_in[10];

    float* out = (float*)d_out;
    int ntok = in_sizes[1];                           // B*N = 8192
    float* out_cnt = out + ((size_t)out_size - ntok); // new_buf first, new_count last
    int w3n = in_sizes[9];                            // 2048*256

    scan_w3_kernel<<<SCAN_BLOCKS, 1024>>>(W3, w3n);
    finalize_kernel<<<1, 1024>>>(b3);
    combo_kernel<<<148, 256>>>(W1, b1, W2, b2, W3, b3);
    combine_kernel<<<ntok, 256>>>(L, lcnt, R, rcnt, subs, out, out_cnt);
}